// round 9
// baseline (speedup 1.0000x reference)
#include <cuda_runtime.h>
#include <cuda_fp16.h>
#include <math.h>

#define NUM_CLASSES 200
#define NUM_PROTO   10
#define EMBED_D     512
#define NQ          8192
#define MC          96          // hard cap tokens/class (mean 41, sd 6.4)
#define EPSILON_    0.01f
#define ITERS       5
#define MOM         0.02f

// ---------------- device scratch (allocation-free) ----------------
__device__ __half2 g_tokn[NQ * 256];            // normalized tokens fp16 (8 MB)
__device__ float   g_S[NUM_CLASSES * NUM_PROTO * MC];
__device__ int     g_idx[NQ];
__device__ int     g_off[NUM_CLASSES + 1];
__device__ int     g_cur[NUM_CLASSES];
__device__ int     g_cnt[NUM_CLASSES];          // zero-init; re-zeroed by kF

__device__ __forceinline__ void cp16(unsigned dst, const void* src) {
    asm volatile("cp.async.cg.shared.global [%0], [%1], 16;\n" :: "r"(dst), "l"(src));
}

// dtype detect on the SHARED window words [1..511]: in-bounds for both int32
// (8192 words) and int64 (16384 words) label buffers; identical in all blocks.
__device__ __forceinline__ int detect_is64(const unsigned* W, int tid) {
    unsigned hw = (tid < 256) ? W[2 * tid + 1] : 0u;
    return __syncthreads_or(hw != 0u) ? 0 : 1;
}

// ---------------------------------------------------------------------------
// kA: grid 256 x 256. Block b: normalize token rows [32b,32b+32) -> g_tokn,
//     and histogram labels [32b,32b+32) into g_cnt.
// ---------------------------------------------------------------------------
__global__ void __launch_bounds__(256) kA(const float* __restrict__ tokens,
                                          const void* __restrict__ labels_v)
{
    const int b = blockIdx.x, tid = threadIdx.x;
    const int lane = tid & 31, wid = tid >> 5;
    const unsigned* W = (const unsigned*)labels_v;

    const int is64 = detect_is64(W, tid);

    if (tid < 32) {
        int li = 32 * b + tid;
        int lab = is64 ? (int)W[2 * li] : (int)W[li];
        atomicAdd(&g_cnt[lab], 1);
    }

    // warp per row, 4 rounds
    for (int rr = 0; rr < 4; rr++) {
        int row = 32 * b + wid + 8 * rr;
        const float4* src = (const float4*)(tokens + (size_t)row * EMBED_D);
        float4 r[4];
        float ss = 0.f;
        #pragma unroll
        for (int k = 0; k < 4; k++) {
            r[k] = src[lane + 32 * k];
            ss += r[k].x*r[k].x + r[k].y*r[k].y + r[k].z*r[k].z + r[k].w*r[k].w;
        }
        #pragma unroll
        for (int o = 16; o; o >>= 1) ss += __shfl_xor_sync(0xffffffffu, ss, o);
        float inv = rsqrtf(ss);
        uint2* drow = (uint2*)(g_tokn + (size_t)row * 256);
        #pragma unroll
        for (int k = 0; k < 4; k++) {
            __half2 h01 = __floats2half2_rn(r[k].x * inv, r[k].y * inv);
            __half2 h23 = __floats2half2_rn(r[k].z * inv, r[k].w * inv);
            uint2 u;
            u.x = *(unsigned*)&h01;
            u.y = *(unsigned*)&h23;
            drow[lane + 32 * k] = u;
        }
    }
}

// ---------------------------------------------------------------------------
// kB: 1 block x 256. Inclusive scan of g_cnt -> g_off / g_cur.
// ---------------------------------------------------------------------------
__global__ void __launch_bounds__(256) kB()
{
    __shared__ int a[256];
    int tid = threadIdx.x;
    a[tid] = (tid < NUM_CLASSES) ? g_cnt[tid] : 0;
    __syncthreads();
    for (int off = 1; off < 256; off <<= 1) {
        int v = (tid >= off) ? a[tid - off] : 0;
        __syncthreads();
        a[tid] += v;
        __syncthreads();
    }
    if (tid < NUM_CLASSES) {
        g_off[tid + 1] = a[tid];
        g_cur[tid] = (tid == 0) ? 0 : a[tid - 1];
    }
    if (tid == 0) g_off[0] = 0;
}

// ---------------------------------------------------------------------------
// kC: grid 32 x 256. Scatter token index i into CSR slot of its class.
// ---------------------------------------------------------------------------
__global__ void __launch_bounds__(256) kC(const void* __restrict__ labels_v)
{
    const int bc = blockIdx.x, tid = threadIdx.x;
    const unsigned* W = (const unsigned*)labels_v;
    const int is64 = detect_is64(W, tid);
    int i = 256 * bc + tid;
    int lab = is64 ? (int)W[2 * i] : (int)W[i];
    int pos = atomicAdd(&g_cur[lab], 1);
    g_idx[pos] = i;
}

// ---------------------------------------------------------------------------
// kS: grid 400 = (class, row-half) x 320 threads.
//     Stage <=48 fp16 rows to smem, 5 proto-pairs (regs) x 2 row-subsets,
//     write S to g_S.
// ---------------------------------------------------------------------------
#define KS_SMEM (48 * 1024 + 256)
extern __shared__ char s_ks[];

__global__ void __launch_bounds__(320) kS(const float* __restrict__ protos_g)
{
    char* srow = s_ks;                           // [48][1024] bytes
    int*  sidx = (int*)(s_ks + 48 * 1024);       // [48]

    const int bid = blockIdx.x;
    const int c = bid >> 1, h = bid & 1;
    const int tid = threadIdx.x, lane = tid & 31, wid = tid >> 5;

    const int off = g_off[c];
    int cnt = g_off[c + 1] - off;
    const int m = (cnt < MC) ? cnt : MC;
    const int half1 = (m + 1) >> 1;
    const int hs = h ? half1 : 0;
    const int he = h ? m : half1;
    const int nrows = he - hs;

    if (tid < nrows) sidx[tid] = g_idx[off + hs + tid];
    __syncthreads();

    // stage rows (fp16, 1KB each) via cp.async
    {
        unsigned sb = (unsigned)__cvta_generic_to_shared(srow);
        for (int t = tid; t < nrows * 64; t += 320) {
            int r = t >> 6, q = t & 63;
            cp16(sb + (unsigned)(r * 1024 + q * 16),
                 (const char*)(g_tokn + (size_t)sidx[r] * 256) + q * 16);
        }
        asm volatile("cp.async.commit_group;\n");
    }

    // load this warp's 2 protos into registers (elements 16*lane..16*lane+15)
    const int q = wid >> 1, s = wid & 1;
    float pa[16], pb[16];
    {
        const float4* P0 = (const float4*)(protos_g + ((size_t)c * NUM_PROTO + 2 * q) * EMBED_D + 16 * lane);
        const float4* P1 = (const float4*)(protos_g + ((size_t)c * NUM_PROTO + 2 * q + 1) * EMBED_D + 16 * lane);
        #pragma unroll
        for (int k = 0; k < 4; k++) {
            float4 v0 = P0[k], v1 = P1[k];
            pa[4*k] = v0.x; pa[4*k+1] = v0.y; pa[4*k+2] = v0.z; pa[4*k+3] = v0.w;
            pb[4*k] = v1.x; pb[4*k+1] = v1.y; pb[4*k+2] = v1.z; pb[4*k+3] = v1.w;
        }
    }
    asm volatile("cp.async.wait_group 0;\n");
    __syncthreads();

    for (int r = s; r < nrows; r += 2) {
        const char* rp = srow + r * 1024 + lane * 32;
        union { uint4 u; __half2 hh[4]; } A, B;
        A.u = *(const uint4*)rp;
        B.u = *(const uint4*)(rp + 16);
        float d0 = 0.f, d1 = 0.f;
        #pragma unroll
        for (int t = 0; t < 4; t++) {
            float2 f = __half22float2(A.hh[t]);
            d0 += f.x * pa[2*t]     + f.y * pa[2*t+1];
            d1 += f.x * pb[2*t]     + f.y * pb[2*t+1];
        }
        #pragma unroll
        for (int t = 0; t < 4; t++) {
            float2 f = __half22float2(B.hh[t]);
            d0 += f.x * pa[8+2*t]   + f.y * pa[8+2*t+1];
            d1 += f.x * pb[8+2*t]   + f.y * pb[8+2*t+1];
        }
        #pragma unroll
        for (int o = 16; o; o >>= 1) {
            d0 += __shfl_xor_sync(0xffffffffu, d0, o);
            d1 += __shfl_xor_sync(0xffffffffu, d1, o);
        }
        if (lane == 0) {
            int jg = hs + r;
            g_S[(size_t)c * (NUM_PROTO * MC) + (2*q) * MC + jg]     = d0;
            g_S[(size_t)c * (NUM_PROTO * MC) + (2*q + 1) * MC + jg] = d1;
        }
    }
}

// ---------------------------------------------------------------------------
// kF: grid 200 x 512. Sinkhorn + pi_ @ tok + blend + l2norm + write.
// ---------------------------------------------------------------------------
#define KF_S_OFF   0
#define KF_SV_OFF  (NUM_PROTO * MC * 4)
#define KF_IDX_OFF (KF_SV_OFF + MC * 4)
#define KF_STG_OFF (KF_IDX_OFF + MC * 4)
#define KF_SMEM    (KF_STG_OFF + 2 * NUM_PROTO * 256 * 8)
extern __shared__ char s_kf[];

__global__ void __launch_bounds__(512) kF(const float* __restrict__ protos_g,
                                          float* __restrict__ out)
{
    __shared__ float su[NUM_PROTO];
    float*  sS   = (float*)(s_kf + KF_S_OFF);
    float*  sv   = (float*)(s_kf + KF_SV_OFF);
    int*    sidx = (int*)(s_kf + KF_IDX_OFF);
    float2* stage = (float2*)(s_kf + KF_STG_OFF);

    const int c = blockIdx.x;
    const int tid = threadIdx.x, lane = tid & 31, wid = tid >> 5;

    const int off = g_off[c];
    int cnt = g_off[c + 1] - off;
    const int m = (cnt < MC) ? cnt : MC;

    for (int i = tid; i < NUM_PROTO * MC; i += 512)
        sS[i] = g_S[(size_t)c * (NUM_PROTO * MC) + i];
    if (tid < m)  sidx[tid] = g_idx[off + tid];
    if (tid < MC) sv[tid] = 0.f;
    if (tid < NUM_PROTO) su[tid] = 0.f;
    __syncthreads();

    if (m > 0) {
        const float log_a = logf(1.0f / (float)NUM_PROTO + 1e-8f);
        const float log_b = logf(1.0f / (float)m + 1e-8f);
        const float inv_eps = 1.0f / EPSILON_;

        for (int it = 0; it < ITERS; it++) {
            if (wid < NUM_PROTO) {           // u: warp p
                int p = wid;
                float up = su[p];
                float mx = -INFINITY;
                for (int j = lane; j < m; j += 32)
                    mx = fmaxf(mx, (sS[p * MC + j] + up + sv[j]) * inv_eps);
                #pragma unroll
                for (int o = 16; o; o >>= 1)
                    mx = fmaxf(mx, __shfl_xor_sync(0xffffffffu, mx, o));
                float sum = 0.f;
                for (int j = lane; j < m; j += 32)
                    sum += expf((sS[p * MC + j] + up + sv[j]) * inv_eps - mx);
                #pragma unroll
                for (int o = 16; o; o >>= 1)
                    sum += __shfl_xor_sync(0xffffffffu, sum, o);
                if (lane == 0)
                    su[p] = EPSILON_ * (log_a - (mx + logf(sum))) + up;
            }
            __syncthreads();
            if (tid < m) {                   // v: thread j
                int j = tid;
                float vj = sv[j];
                float mx = -INFINITY;
                #pragma unroll
                for (int p = 0; p < NUM_PROTO; p++)
                    mx = fmaxf(mx, (sS[p * MC + j] + su[p] + vj) * inv_eps);
                float sum = 0.f;
                #pragma unroll
                for (int p = 0; p < NUM_PROTO; p++)
                    sum += expf((sS[p * MC + j] + su[p] + vj) * inv_eps - mx);
                sv[j] = EPSILON_ * (log_b - (mx + logf(sum))) + vj;
            }
            __syncthreads();
        }
        if (tid < m) {                       // pi, column-normalized in place
            int j = tid;
            float col[NUM_PROTO];
            float cs = 0.f;
            #pragma unroll
            for (int p = 0; p < NUM_PROTO; p++) {
                col[p] = expf((sS[p * MC + j] + su[p] + sv[j]) * (1.0f / EPSILON_));
                cs += col[p];
            }
            float inv = 1.0f / cs;
            #pragma unroll
            for (int p = 0; p < NUM_PROTO; p++) sS[p * MC + j] = col[p] * inv;
        }
    }
    __syncthreads();

    // pi_ @ tok : 2 j-groups x 256 half2-dims
    const int g  = tid >> 8;
    const int d2 = tid & 255;
    float2 acc[NUM_PROTO];
    #pragma unroll
    for (int p = 0; p < NUM_PROTO; p++) acc[p] = make_float2(0.f, 0.f);

    #pragma unroll 4
    for (int j = g; j < m; j += 2) {
        float2 t2 = __half22float2(g_tokn[(size_t)sidx[j] * 256 + d2]);
        #pragma unroll
        for (int p = 0; p < NUM_PROTO; p++) {
            float w = sS[p * MC + j];
            acc[p].x += w * t2.x;
            acc[p].y += w * t2.y;
        }
    }
    #pragma unroll
    for (int p = 0; p < NUM_PROTO; p++)
        stage[(g * NUM_PROTO + p) * 256 + d2] = acc[p];
    __syncthreads();

    // epilogue: warp p reduces groups, blends, l2-normalizes, writes
    if (wid < NUM_PROTO) {
        const int p = wid;
        float2 v[8];
        float ss = 0.f;
        const float2* pr2 = (const float2*)(protos_g + ((size_t)c * NUM_PROTO + p) * EMBED_D);
        #pragma unroll
        for (int qq = 0; qq < 8; qq++) {
            int dd = lane + 32 * qq;
            float2 a = stage[(0 * NUM_PROTO + p) * 256 + dd];
            float2 b = stage[(1 * NUM_PROTO + p) * 256 + dd];
            float2 pr = pr2[dd];
            v[qq].x = (1.0f - MOM) * pr.x + MOM * (a.x + b.x);
            v[qq].y = (1.0f - MOM) * pr.y + MOM * (a.y + b.y);
            ss += v[qq].x * v[qq].x + v[qq].y * v[qq].y;
        }
        #pragma unroll
        for (int o = 16; o; o >>= 1) ss += __shfl_xor_sync(0xffffffffu, ss, o);
        float inv = rsqrtf(ss);
        float2* dst = (float2*)(out + ((size_t)(c * NUM_PROTO + p)) * EMBED_D);
        #pragma unroll
        for (int qq = 0; qq < 8; qq++) {
            float2 o2;
            o2.x = v[qq].x * inv;
            o2.y = v[qq].y * inv;
            dst[lane + 32 * qq] = o2;
        }
    }

    if (tid == 0) g_cnt[c] = 0;   // reset histogram for next graph replay
}

// ---------------------------------------------------------------------------
extern "C" void kernel_launch(void* const* d_in, const int* in_sizes, int n_in,
                              void* d_out, int out_size) {
    const float* tokens = (const float*)d_in[0];
    const void*  labels = d_in[1];
    const float* protos = (const float*)d_in[2];
    float* out = (float*)d_out;

    cudaFuncSetAttribute(kS, cudaFuncAttributeMaxDynamicSharedMemorySize, KS_SMEM);
    cudaFuncSetAttribute(kF, cudaFuncAttributeMaxDynamicSharedMemorySize, KF_SMEM);

    kA<<<256, 256>>>(tokens, labels);
    kB<<<1, 256>>>();
    kC<<<32, 256>>>(labels);
    kS<<<400, 320, KS_SMEM>>>(protos);
    kF<<<200, 512, KF_SMEM>>>(protos, out);
}

// round 10
// speedup vs baseline: 1.3122x; 1.3122x over previous
#include <cuda_runtime.h>
#include <cuda_fp16.h>
#include <math.h>

#define NUM_CLASSES 200
#define NUM_PROTO   10
#define EMBED_D     512
#define NQ          8192
#define MC          96      // S/sv/idx capacity
#define TCAP        64      // fp16 rows staged in smem (max plausible m ~60)
#define EPSILON_    0.01f
#define ITERS       5
#define MOM         0.02f
#define NT          512

// dynamic smem layout (bytes)
#define OFFB_TOKH  0                        // 64 rows x 1KB fp16 = 65536
#define OFFB_S     65536                    // 10*96*4 = 3840
#define OFFB_SV    (OFFB_S + NUM_PROTO * MC * 4)
#define OFFB_INVN  (OFFB_SV + MC * 4)
#define OFFB_IDX   (OFFB_INVN + MC * 4)
#define SMEM_BYTES (OFFB_IDX + MC * 4)      // 70528

extern __shared__ char smc[];

__global__ void __launch_bounds__(NT, 2) fused_kernel(
    const float* __restrict__ tokens,
    const void*  __restrict__ labels_v,
    const float* __restrict__ protos_g,
    float* __restrict__ out)
{
    __shared__ float su[NUM_PROTO];
    __shared__ int   s_cnt;

    __half2* tok_h = (__half2*)(smc + OFFB_TOKH);   // [TCAP][256]
    float*   sS    = (float*)(smc + OFFB_S);
    float*   sv    = (float*)(smc + OFFB_SV);
    float*   invn  = (float*)(smc + OFFB_INVN);
    int*     idx   = (int*)(smc + OFFB_IDX);

    const int c    = blockIdx.x;
    const int tid  = threadIdx.x;
    const int lane = tid & 31;
    const int wid  = tid >> 5;

    if (tid == 0) s_cnt = 0;
    if (tid < NUM_PROTO) su[tid] = 0.f;
    if (tid < MC)        sv[tid] = 0.f;

    // ---- dtype detect: int64 labels (<200) have zero high words ----
    unsigned hwd = ((const unsigned*)labels_v)[2 * tid + 1];
    const int is64 = __syncthreads_or(hwd != 0u) ? 0 : 1;  // barrier orders s_cnt

    // ---- label scan: wide int4 loads, all in flight at once ----
    if (is64) {
        int4 v[8];
        const int4* L = (const int4*)labels_v;          // 2 labels per int4
        #pragma unroll
        for (int k = 0; k < 8; k++) v[k] = L[tid + NT * k];
        #pragma unroll
        for (int k = 0; k < 8; k++) {
            int base = 2 * (tid + NT * k);
            if (v[k].x == c) { int p = atomicAdd(&s_cnt, 1); if (p < MC) idx[p] = base; }
            if (v[k].z == c) { int p = atomicAdd(&s_cnt, 1); if (p < MC) idx[p] = base + 1; }
        }
    } else {
        int4 v[4];
        const int4* L = (const int4*)labels_v;          // 4 labels per int4
        #pragma unroll
        for (int k = 0; k < 4; k++) v[k] = L[tid + NT * k];
        #pragma unroll
        for (int k = 0; k < 4; k++) {
            int base = 4 * (tid + NT * k);
            if (v[k].x == c) { int p = atomicAdd(&s_cnt, 1); if (p < MC) idx[p] = base; }
            if (v[k].y == c) { int p = atomicAdd(&s_cnt, 1); if (p < MC) idx[p] = base + 1; }
            if (v[k].z == c) { int p = atomicAdd(&s_cnt, 1); if (p < MC) idx[p] = base + 2; }
            if (v[k].w == c) { int p = atomicAdd(&s_cnt, 1); if (p < MC) idx[p] = base + 3; }
        }
    }
    __syncthreads();
    const int m = (s_cnt < MC) ? s_cnt : MC;

    // ---- Pre-pass: warp per row: load fp32, normalize, stage fp16 ----
    for (int j = wid; j < m; j += 16) {
        const float4* tk = (const float4*)(tokens + (size_t)idx[j] * EMBED_D);
        float4 r[4];
        float ss = 0.f;
        #pragma unroll
        for (int k = 0; k < 4; k++) {
            r[k] = tk[lane + 32 * k];
            ss += r[k].x*r[k].x + r[k].y*r[k].y + r[k].z*r[k].z + r[k].w*r[k].w;
        }
        #pragma unroll
        for (int o = 16; o; o >>= 1) ss += __shfl_xor_sync(0xffffffffu, ss, o);
        float inv = rsqrtf(ss);
        if (lane == 0) invn[j] = inv;
        if (j < TCAP) {
            __half2* row = tok_h + (size_t)j * 256;
            #pragma unroll
            for (int k = 0; k < 4; k++) {
                int h2 = (lane + 32 * k) * 2;
                row[h2]     = __floats2half2_rn(r[k].x * inv, r[k].y * inv);
                row[h2 + 1] = __floats2half2_rn(r[k].z * inv, r[k].w * inv);
            }
        }
    }
    __syncthreads();

    // ---- Phase 2: 5 proto-pairs x 3 row-subsets; protos in regs,
    //      rows from fp16 smem (no global token re-reads) ----
    if (wid < 15) {
        const int q  = wid / 3;
        const int rs = wid - 3 * q;
        // proto elements [16*lane, 16*lane+16) for protos 2q, 2q+1
        float pa[16], pb[16];
        {
            const float4* P0 = (const float4*)(protos_g + ((size_t)c * NUM_PROTO + 2*q)     * EMBED_D + 16 * lane);
            const float4* P1 = (const float4*)(protos_g + ((size_t)c * NUM_PROTO + 2*q + 1) * EMBED_D + 16 * lane);
            #pragma unroll
            for (int k = 0; k < 4; k++) {
                float4 v0 = P0[k], v1 = P1[k];
                pa[4*k] = v0.x; pa[4*k+1] = v0.y; pa[4*k+2] = v0.z; pa[4*k+3] = v0.w;
                pb[4*k] = v1.x; pb[4*k+1] = v1.y; pb[4*k+2] = v1.z; pb[4*k+3] = v1.w;
            }
        }
        for (int j = rs; j < m; j += 3) {
            float d0 = 0.f, d1 = 0.f;
            if (j < TCAP) {
                const char* rp = (const char*)tok_h + (size_t)j * 1024 + lane * 32;
                union { uint4 u; __half2 hh[4]; } A, B;
                A.u = *(const uint4*)rp;
                B.u = *(const uint4*)(rp + 16);
                #pragma unroll
                for (int t = 0; t < 4; t++) {
                    float2 f = __half22float2(A.hh[t]);
                    d0 += f.x * pa[2*t]   + f.y * pa[2*t+1];
                    d1 += f.x * pb[2*t]   + f.y * pb[2*t+1];
                }
                #pragma unroll
                for (int t = 0; t < 4; t++) {
                    float2 f = __half22float2(B.hh[t]);
                    d0 += f.x * pa[8+2*t] + f.y * pa[8+2*t+1];
                    d1 += f.x * pb[8+2*t] + f.y * pb[8+2*t+1];
                }
            } else {   // rare fallback: fp32 global x invn
                const float4* tk = (const float4*)(tokens + (size_t)idx[j] * EMBED_D + 16 * lane);
                float iv = invn[j];
                #pragma unroll
                for (int k = 0; k < 4; k++) {
                    float4 t = tk[k];
                    d0 += pa[4*k]*t.x + pa[4*k+1]*t.y + pa[4*k+2]*t.z + pa[4*k+3]*t.w;
                    d1 += pb[4*k]*t.x + pb[4*k+1]*t.y + pb[4*k+2]*t.z + pb[4*k+3]*t.w;
                }
                d0 *= iv; d1 *= iv;
            }
            #pragma unroll
            for (int o = 16; o; o >>= 1) {
                d0 += __shfl_xor_sync(0xffffffffu, d0, o);
                d1 += __shfl_xor_sync(0xffffffffu, d1, o);
            }
            if (lane == 0) {
                sS[(2*q)     * MC + j] = d0;
                sS[(2*q + 1) * MC + j] = d1;
            }
        }
    }
    __syncthreads();

    // ---- Phase 3: Sinkhorn (warps 0-9 only; named barrier 1, 320 thr) ----
    if (m > 0 && wid < NUM_PROTO) {
        const float log_a = __logf(1.0f / (float)NUM_PROTO + 1e-8f);
        const float log_b = __logf(1.0f / (float)m + 1e-8f);
        const float inv_eps = 1.0f / EPSILON_;
        const int p = wid;

        // hoist this warp's S row (3 elems/lane) and this thread's S column
        const float s0 = (lane      < m) ? sS[p * MC + lane]      : -INFINITY;
        const float s1 = (lane + 32 < m) ? sS[p * MC + lane + 32] : -INFINITY;
        const float s2 = (lane + 64 < m) ? sS[p * MC + lane + 64] : -INFINITY;
        float scol[NUM_PROTO];
        if (tid < m) {
            #pragma unroll
            for (int pp = 0; pp < NUM_PROTO; pp++) scol[pp] = sS[pp * MC + tid];
        }

        for (int it = 0; it < ITERS; it++) {
            // u-update (all 10 warps work)
            {
                float up = su[p];
                float t0 = (s0 + up + sv[lane])      * inv_eps;
                float t1 = (s1 + up + sv[lane + 32]) * inv_eps;
                float t2 = (s2 + up + sv[lane + 64]) * inv_eps;
                float mx = fmaxf(t0, fmaxf(t1, t2));
                #pragma unroll
                for (int o = 16; o; o >>= 1)
                    mx = fmaxf(mx, __shfl_xor_sync(0xffffffffu, mx, o));
                float sum = __expf(t0 - mx) + __expf(t1 - mx) + __expf(t2 - mx);
                #pragma unroll
                for (int o = 16; o; o >>= 1)
                    sum += __shfl_xor_sync(0xffffffffu, sum, o);
                if (lane == 0)
                    su[p] = EPSILON_ * (log_a - (mx + __logf(sum))) + up;
            }
            asm volatile("bar.sync 1, 320;" ::: "memory");
            // v-update (threads < m)
            if (tid < m) {
                float vj = sv[tid];
                float mx = -INFINITY;
                #pragma unroll
                for (int pp = 0; pp < NUM_PROTO; pp++)
                    mx = fmaxf(mx, (scol[pp] + su[pp] + vj) * inv_eps);
                float sum = 0.f;
                #pragma unroll
                for (int pp = 0; pp < NUM_PROTO; pp++)
                    sum += __expf((scol[pp] + su[pp] + vj) * inv_eps - mx);
                sv[tid] = EPSILON_ * (log_b - (mx + __logf(sum))) + vj;
            }
            asm volatile("bar.sync 1, 320;" ::: "memory");
        }

        // pi = exp(kernel); column-normalize -> pi_ (col lse == log_b < 0)
        if (tid < m) {
            float vj = sv[tid];
            float col[NUM_PROTO];
            float cs = 0.f;
            #pragma unroll
            for (int pp = 0; pp < NUM_PROTO; pp++) {
                col[pp] = __expf((scol[pp] + su[pp] + vj) * inv_eps);
                cs += col[pp];
            }
            float inv = 1.0f / cs;
            #pragma unroll
            for (int pp = 0; pp < NUM_PROTO; pp++) sS[pp * MC + tid] = col[pp] * inv;
        }
    }
    __syncthreads();

    // ---- Phase 4: new_proto = pi_ @ tok; 2 j-groups x 256 half2-dims ----
    const int g  = tid >> 8;
    const int d2 = tid & 255;
    float2 acc[NUM_PROTO];
    #pragma unroll
    for (int p = 0; p < NUM_PROTO; p++) acc[p] = make_float2(0.f, 0.f);

    for (int j = g; j < m; j += 2) {
        float2 t2;
        if (j < TCAP) {
            t2 = __half22float2(tok_h[(size_t)j * 256 + d2]);
        } else {
            const float2* tr = (const float2*)(tokens + (size_t)idx[j] * EMBED_D);
            t2 = tr[d2];
            float iv = invn[j];
            t2.x *= iv; t2.y *= iv;
        }
        #pragma unroll
        for (int p = 0; p < NUM_PROTO; p++) {
            float w = sS[p * MC + j];
            acc[p].x += w * t2.x;
            acc[p].y += w * t2.y;
        }
    }
    __syncthreads();                 // all reads of tok_h done
    float2* stage = (float2*)(smc + OFFB_TOKH);   // reuse: [2][10][256] float2
    #pragma unroll
    for (int p = 0; p < NUM_PROTO; p++)
        stage[(g * NUM_PROTO + p) * 256 + d2] = acc[p];
    __syncthreads();

    // ---- epilogue: warp p reduces groups, blends, l2-normalizes, writes ----
    if (wid < NUM_PROTO) {
        const int p = wid;
        float2 v[8];
        float ss = 0.f;
        const float2* pr2 = (const float2*)(protos_g + ((size_t)c * NUM_PROTO + p) * EMBED_D);
        #pragma unroll
        for (int qq = 0; qq < 8; qq++) {
            int dd = lane + 32 * qq;
            float2 a = stage[(0 * NUM_PROTO + p) * 256 + dd];
            float2 b = stage[(1 * NUM_PROTO + p) * 256 + dd];
            float2 pr = pr2[dd];
            v[qq].x = (1.0f - MOM) * pr.x + MOM * (a.x + b.x);
            v[qq].y = (1.0f - MOM) * pr.y + MOM * (a.y + b.y);
            ss += v[qq].x * v[qq].x + v[qq].y * v[qq].y;
        }
        #pragma unroll
        for (int o = 16; o; o >>= 1) ss += __shfl_xor_sync(0xffffffffu, ss, o);
        float inv = rsqrtf(ss);
        float2* dst = (float2*)(out + ((size_t)(c * NUM_PROTO + p)) * EMBED_D);
        #pragma unroll
        for (int qq = 0; qq < 8; qq++) {
            float2 o2;
            o2.x = v[qq].x * inv;
            o2.y = v[qq].y * inv;
            dst[lane + 32 * qq] = o2;
        }
    }
}

// ---------------------------------------------------------------------------
extern "C" void kernel_launch(void* const* d_in, const int* in_sizes, int n_in,
                              void* d_out, int out_size) {
    const float* tokens = (const float*)d_in[0];
    const void*  labels = d_in[1];
    const float* protos = (const float*)d_in[2];
    float* out = (float*)d_out;

    cudaFuncSetAttribute(fused_kernel,
                         cudaFuncAttributeMaxDynamicSharedMemorySize, SMEM_BYTES);
    fused_kernel<<<NUM_CLASSES, NT, SMEM_BYTES>>>(tokens, labels, protos, out);
}

// round 12
// speedup vs baseline: 1.8425x; 1.4041x over previous
#include <cuda_runtime.h>
#include <cuda_fp16.h>
#include <math.h>

#define NUM_CLASSES 200
#define NUM_PROTO   10
#define EMBED_D     512
#define NQ          8192
#define MC          96      // S/sv/idx capacity
#define TCAP        64      // fp16 rows staged in smem
#define EPSILON_    0.01f
#define ITERS       5
#define MOM         0.02f
#define NT          512
#define ROWB        1040    // bytes per staged fp16 row (520 halves, bank-staggered)

// dynamic smem layout (bytes), all 16B aligned
#define OFFB_TOKH   0                       // 64 * 1040 = 66560
#define OFFB_PROTOH 66560                   // 16 * 1040 = 16640 (rows 10-15 unwritten, predicated out)
#define OFFB_S      83200                   // 10*96*4 = 3840
#define OFFB_SV     87040                   // 96*4
#define OFFB_INVN   87424                   // 96*4
#define OFFB_IDX    87808                   // 96*4
#define SMEM_BYTES  88192

extern __shared__ char smc[];

__device__ __forceinline__ void ldm_x4(unsigned addr, unsigned &a0, unsigned &a1,
                                       unsigned &a2, unsigned &a3) {
    asm volatile("ldmatrix.sync.aligned.m8n8.x4.shared.b16 {%0,%1,%2,%3}, [%4];"
        : "=r"(a0), "=r"(a1), "=r"(a2), "=r"(a3) : "r"(addr));
}
__device__ __forceinline__ void ldm_x2(unsigned addr, unsigned &b0, unsigned &b1) {
    asm volatile("ldmatrix.sync.aligned.m8n8.x2.shared.b16 {%0,%1}, [%2];"
        : "=r"(b0), "=r"(b1) : "r"(addr));
}
__device__ __forceinline__ void mma16816(float &c0, float &c1, float &c2, float &c3,
                                         unsigned a0, unsigned a1, unsigned a2, unsigned a3,
                                         unsigned b0, unsigned b1) {
    asm volatile("mma.sync.aligned.m16n8k16.row.col.f32.f16.f16.f32 "
        "{%0,%1,%2,%3},{%4,%5,%6,%7},{%8,%9},{%0,%1,%2,%3};"
        : "+f"(c0), "+f"(c1), "+f"(c2), "+f"(c3)
        : "r"(a0), "r"(a1), "r"(a2), "r"(a3), "r"(b0), "r"(b1));
}

__global__ void __launch_bounds__(NT, 2) fused_kernel(
    const float* __restrict__ tokens,
    const void*  __restrict__ labels_v,
    const float* __restrict__ protos_g,
    float* __restrict__ out)
{
    __shared__ float su[NUM_PROTO];
    __shared__ int   s_cnt;

    float* sS   = (float*)(smc + OFFB_S);
    float* sv   = (float*)(smc + OFFB_SV);
    float* invn = (float*)(smc + OFFB_INVN);
    int*   idx  = (int*)(smc + OFFB_IDX);

    const int c    = blockIdx.x;
    const int tid  = threadIdx.x;
    const int lane = tid & 31;
    const int wid  = tid >> 5;

    if (tid == 0) s_cnt = 0;
    if (tid < NUM_PROTO) su[tid] = 0.f;
    if (tid < MC)        sv[tid] = 0.f;

    // ---- dtype detect: int64 labels (<200) have zero high words ----
    unsigned hwd = ((const unsigned*)labels_v)[2 * tid + 1];
    const int is64 = __syncthreads_or(hwd != 0u) ? 0 : 1;  // barrier orders s_cnt

    // ---- proto fp32 -> fp16 smem [rows 0-9 valid] ----
    {
        const float4* pg = (const float4*)(protos_g + (size_t)c * NUM_PROTO * EMBED_D);
        for (int t = tid; t < NUM_PROTO * EMBED_D / 4; t += NT) {
            float4 v = pg[t];
            int p = t >> 7, d4 = t & 127;
            __half2* dst = (__half2*)(smc + OFFB_PROTOH + p * ROWB) + d4 * 2;
            dst[0] = __floats2half2_rn(v.x, v.y);
            dst[1] = __floats2half2_rn(v.z, v.w);
        }
    }

    // ---- label scan: wide int4 loads, all in flight at once ----
    if (is64) {
        int4 v[8];
        const int4* L = (const int4*)labels_v;          // 2 labels per int4
        #pragma unroll
        for (int k = 0; k < 8; k++) v[k] = L[tid + NT * k];
        #pragma unroll
        for (int k = 0; k < 8; k++) {
            int base = 2 * (tid + NT * k);
            if (v[k].x == c) { int p = atomicAdd(&s_cnt, 1); if (p < MC) idx[p] = base; }
            if (v[k].z == c) { int p = atomicAdd(&s_cnt, 1); if (p < MC) idx[p] = base + 1; }
        }
    } else {
        int4 v[4];
        const int4* L = (const int4*)labels_v;          // 4 labels per int4
        #pragma unroll
        for (int k = 0; k < 4; k++) v[k] = L[tid + NT * k];
        #pragma unroll
        for (int k = 0; k < 4; k++) {
            int base = 4 * (tid + NT * k);
            if (v[k].x == c) { int p = atomicAdd(&s_cnt, 1); if (p < MC) idx[p] = base; }
            if (v[k].y == c) { int p = atomicAdd(&s_cnt, 1); if (p < MC) idx[p] = base + 1; }
            if (v[k].z == c) { int p = atomicAdd(&s_cnt, 1); if (p < MC) idx[p] = base + 2; }
            if (v[k].w == c) { int p = atomicAdd(&s_cnt, 1); if (p < MC) idx[p] = base + 3; }
        }
    }
    __syncthreads();
    const int m = (s_cnt < MC) ? s_cnt : MC;

    // ---- Pre-pass: warp per row: load fp32, normalize, stage fp16 ----
    for (int j = wid; j < m; j += 16) {
        const float4* tk = (const float4*)(tokens + (size_t)idx[j] * EMBED_D);
        float4 r[4];
        float ss = 0.f;
        #pragma unroll
        for (int k = 0; k < 4; k++) {
            r[k] = tk[lane + 32 * k];
            ss += r[k].x*r[k].x + r[k].y*r[k].y + r[k].z*r[k].z + r[k].w*r[k].w;
        }
        #pragma unroll
        for (int o = 16; o; o >>= 1) ss += __shfl_xor_sync(0xffffffffu, ss, o);
        float inv = rsqrtf(ss);
        if (lane == 0) invn[j] = inv;
        if (j < TCAP) {
            __half2* row = (__half2*)(smc + OFFB_TOKH + j * ROWB);
            #pragma unroll
            for (int k = 0; k < 4; k++) {
                int h2 = (lane + 32 * k) * 2;
                row[h2]     = __floats2half2_rn(r[k].x * inv, r[k].y * inv);
                row[h2 + 1] = __floats2half2_rn(r[k].z * inv, r[k].w * inv);
            }
        }
    }
    __syncthreads();

    // ---- Phase 2: S = proto @ tok_norm^T via tensor cores ----
    // Warps 0-7: C tile [16 p-rows] x [8 j-cols], j-tile = wid*8, 32 k-steps.
    // B rows are ALREADY normalized (staged that way) -> no invn at writeout.
    if (wid < 8) {
        const int jt = wid * 8;
        const int g  = lane >> 3;       // address group 0..3
        const int r8 = lane & 7;
        // A (proto_h): g0:m0-7@k0  g1:m8-15@k0  g2:m0-7@k8  g3:m8-15@k8
        unsigned a_base = (unsigned)__cvta_generic_to_shared(
            smc + OFFB_PROTOH + ((g & 1) * 8 + r8) * ROWB + (g >> 1) * 16);
        // B (tok_h rows jt..jt+7): lanes0-7 @k0, lanes8-15 @k8 (x2 ignores 16-31)
        unsigned b_base = (unsigned)__cvta_generic_to_shared(
            smc + OFFB_TOKH + (jt + r8) * ROWB + (g & 1) * 16);
        float c0 = 0.f, c1 = 0.f, c2 = 0.f, c3 = 0.f;
        #pragma unroll 8
        for (int kk = 0; kk < 32; kk++) {
            unsigned a0, a1, a2, a3, b0, b1;
            ldm_x4(a_base + kk * 32, a0, a1, a2, a3);
            ldm_x2(b_base + kk * 32, b0, b1);
            mma16816(c0, c1, c2, c3, a0, a1, a2, a3, b0, b1);
        }
        // write-out: c0:(row,j0) c1:(row,j0+1) c2:(row+8,j0) c3:(row+8,j0+1)
        const int row = lane >> 2;
        const int j0  = jt + 2 * (lane & 3);
        sS[row * MC + j0]     = c0;
        sS[row * MC + j0 + 1] = c1;
        if (row + 8 < NUM_PROTO) {
            sS[(row + 8) * MC + j0]     = c2;
            sS[(row + 8) * MC + j0 + 1] = c3;
        }
    } else if (m > TCAP) {
        // rare fallback: rows 64..m-1 from raw fp32 global -> needs invn
        for (int j = TCAP + (wid - 8); j < m; j += 8) {
            const float4* tk = (const float4*)(tokens + (size_t)idx[j] * EMBED_D + 16 * lane);
            float4 t[4];
            #pragma unroll
            for (int k = 0; k < 4; k++) t[k] = tk[k];
            float iv = invn[j];
            #pragma unroll
            for (int p = 0; p < NUM_PROTO; p++) {
                const __half2* ph = (const __half2*)(smc + OFFB_PROTOH + p * ROWB) + lane * 8;
                float d = 0.f;
                #pragma unroll
                for (int k = 0; k < 4; k++) {
                    float2 f0 = __half22float2(ph[2 * k]);
                    float2 f1 = __half22float2(ph[2 * k + 1]);
                    d += f0.x * t[k].x + f0.y * t[k].y + f1.x * t[k].z + f1.y * t[k].w;
                }
                #pragma unroll
                for (int o = 16; o; o >>= 1) d += __shfl_xor_sync(0xffffffffu, d, o);
                if (lane == 0) sS[p * MC + j] = d * iv;
            }
        }
    }
    __syncthreads();

    // ---- Phase 3: Sinkhorn (warps 0-9; named barrier 1, 320 threads) ----
    if (m > 0 && wid < NUM_PROTO) {
        const float log_a = __logf(1.0f / (float)NUM_PROTO + 1e-8f);
        const float log_b = __logf(1.0f / (float)m + 1e-8f);
        const float inv_eps = 1.0f / EPSILON_;
        const int p = wid;

        const float s0 = (lane      < m) ? sS[p * MC + lane]      : -INFINITY;
        const float s1 = (lane + 32 < m) ? sS[p * MC + lane + 32] : -INFINITY;
        const float s2 = (lane + 64 < m) ? sS[p * MC + lane + 64] : -INFINITY;
        float scol[NUM_PROTO];
        if (tid < m) {
            #pragma unroll
            for (int pp = 0; pp < NUM_PROTO; pp++) scol[pp] = sS[pp * MC + tid];
        }

        for (int it = 0; it < ITERS; it++) {
            {
                float up = su[p];
                float t0 = (s0 + up + sv[lane])      * inv_eps;
                float t1 = (s1 + up + sv[lane + 32]) * inv_eps;
                float t2 = (s2 + up + sv[lane + 64]) * inv_eps;
                float mx = fmaxf(t0, fmaxf(t1, t2));
                #pragma unroll
                for (int o = 16; o; o >>= 1)
                    mx = fmaxf(mx, __shfl_xor_sync(0xffffffffu, mx, o));
                float sum = __expf(t0 - mx) + __expf(t1 - mx) + __expf(t2 - mx);
                #pragma unroll
                for (int o = 16; o; o >>= 1)
                    sum += __shfl_xor_sync(0xffffffffu, sum, o);
                if (lane == 0)
                    su[p] = EPSILON_ * (log_a - (mx + __logf(sum))) + up;
            }
            asm volatile("bar.sync 1, 320;" ::: "memory");
            if (tid < m) {
                float vj = sv[tid];
                float mx = -INFINITY;
                #pragma unroll
                for (int pp = 0; pp < NUM_PROTO; pp++)
                    mx = fmaxf(mx, (scol[pp] + su[pp] + vj) * inv_eps);
                float sum = 0.f;
                #pragma unroll
                for (int pp = 0; pp < NUM_PROTO; pp++)
                    sum += __expf((scol[pp] + su[pp] + vj) * inv_eps - mx);
                sv[tid] = EPSILON_ * (log_b - (mx + __logf(sum))) + vj;
            }
            asm volatile("bar.sync 1, 320;" ::: "memory");
        }

        if (tid < m) {                       // pi, column-normalized in place
            float vj = sv[tid];
            float col[NUM_PROTO];
            float cs = 0.f;
            #pragma unroll
            for (int pp = 0; pp < NUM_PROTO; pp++) {
                col[pp] = __expf((scol[pp] + su[pp] + vj) * inv_eps);
                cs += col[pp];
            }
            float inv = 1.0f / cs;
            #pragma unroll
            for (int pp = 0; pp < NUM_PROTO; pp++) sS[pp * MC + tid] = col[pp] * inv;
        }
    }
    __syncthreads();

    // ---- Phase 4: new_proto = pi_ @ tok; 2 j-groups x 256 half2-dims ----
    const int g4 = tid >> 8;
    const int d2 = tid & 255;
    float2 acc[NUM_PROTO];
    #pragma unroll
    for (int p = 0; p < NUM_PROTO; p++) acc[p] = make_float2(0.f, 0.f);

    for (int j = g4; j < m; j += 2) {
        float2 t2;
        if (j < TCAP) {
            t2 = __half22float2(*((const __half2*)(smc + OFFB_TOKH + j * ROWB) + d2));
        } else {
            const float2* tr = (const float2*)(tokens + (size_t)idx[j] * EMBED_D);
            t2 = tr[d2];
            float iv = invn[j];
            t2.x *= iv; t2.y *= iv;
        }
        #pragma unroll
        for (int p = 0; p < NUM_PROTO; p++) {
            float w = sS[p * MC + j];
            acc[p].x += w * t2.x;
            acc[p].y += w * t2.y;
        }
    }
    __syncthreads();                 // all reads of tok_h done
    float2* stage = (float2*)(smc + OFFB_TOKH);   // reuse: [2][10][256] float2
    #pragma unroll
    for (int p = 0; p < NUM_PROTO; p++)
        stage[(g4 * NUM_PROTO + p) * 256 + d2] = acc[p];
    __syncthreads();

    // ---- epilogue: warp p reduces groups, blends, l2-normalizes, writes ----
    if (wid < NUM_PROTO) {
        const int p = wid;
        float2 v[8];
        float ss = 0.f;
        const float2* pr2 = (const float2*)(protos_g + ((size_t)c * NUM_PROTO + p) * EMBED_D);
        #pragma unroll
        for (int qq = 0; qq < 8; qq++) {
            int dd = lane + 32 * qq;
            float2 a = stage[(0 * NUM_PROTO + p) * 256 + dd];
            float2 b = stage[(1 * NUM_PROTO + p) * 256 + dd];
            float2 pr = pr2[dd];
            v[qq].x = (1.0f - MOM) * pr.x + MOM * (a.x + b.x);
            v[qq].y = (1.0f - MOM) * pr.y + MOM * (a.y + b.y);
            ss += v[qq].x * v[qq].x + v[qq].y * v[qq].y;
        }
        #pragma unroll
        for (int o = 16; o; o >>= 1) ss += __shfl_xor_sync(0xffffffffu, ss, o);
        float inv = rsqrtf(ss);
        float2* dst = (float2*)(out + ((size_t)(c * NUM_PROTO + p)) * EMBED_D);
        #pragma unroll
        for (int qq = 0; qq < 8; qq++) {
            float2 o2;
            o2.x = v[qq].x * inv;
            o2.y = v[qq].y * inv;
            dst[lane + 32 * qq] = o2;
        }
    }
}

// ---------------------------------------------------------------------------
extern "C" void kernel_launch(void* const* d_in, const int* in_sizes, int n_in,
                              void* d_out, int out_size) {
    const float* tokens = (const float*)d_in[0];
    const void*  labels = d_in[1];
    const float* protos = (const float*)d_in[2];
    float* out = (float*)d_out;

    cudaFuncSetAttribute(fused_kernel,
                         cudaFuncAttributeMaxDynamicSharedMemorySize, SMEM_BYTES);
    fused_kernel<<<NUM_CLASSES, NT, SMEM_BYTES>>>(tokens, labels, protos, out);
}

// round 13
// speedup vs baseline: 2.3351x; 1.2674x over previous
#include <cuda_runtime.h>
#include <cuda_fp16.h>
#include <math.h>

#define NUM_CLASSES 200
#define NUM_PROTO   10
#define EMBED_D     512
#define NQ          8192
#define MC          96      // S/sv/idx capacity
#define TCAP        64      // fp16 rows staged in smem
#define EPSILON_    0.01f
#define ITERS       5
#define MOM         0.02f
#define NT          512
#define ROWB        1040    // bytes per staged fp16 row (520 halves, bank-staggered)
#define PIK         104     // pi_h K padding (208B row stride: conflict-free ldmatrix)
#define STG_W       516     // stage row stride in floats (2064B: conflict-free)

// dynamic smem layout (bytes), all 16B aligned
#define OFFB_TOKH   0                       // 64 * 1040 = 66560 (later: stage [10][516] f32)
#define OFFB_PROTOH 66560                   // 16 * 1040 = 16640
#define OFFB_S      83200                   // 10*96*4 = 3840
#define OFFB_SV     87040                   // 96*4
#define OFFB_INVN   87424                   // 96*4
#define OFFB_IDX    87808                   // 96*4
#define OFFB_PIH    88192                   // 16 * 208 = 3328 fp16 pi
#define SMEM_BYTES  91520

extern __shared__ char smc[];

__device__ __forceinline__ void ldm_x4(unsigned addr, unsigned &a0, unsigned &a1,
                                       unsigned &a2, unsigned &a3) {
    asm volatile("ldmatrix.sync.aligned.m8n8.x4.shared.b16 {%0,%1,%2,%3}, [%4];"
        : "=r"(a0), "=r"(a1), "=r"(a2), "=r"(a3) : "r"(addr));
}
__device__ __forceinline__ void ldm_x2(unsigned addr, unsigned &b0, unsigned &b1) {
    asm volatile("ldmatrix.sync.aligned.m8n8.x2.shared.b16 {%0,%1}, [%2];"
        : "=r"(b0), "=r"(b1) : "r"(addr));
}
__device__ __forceinline__ void ldm_x2t(unsigned addr, unsigned &b0, unsigned &b1) {
    asm volatile("ldmatrix.sync.aligned.m8n8.x2.trans.shared.b16 {%0,%1}, [%2];"
        : "=r"(b0), "=r"(b1) : "r"(addr));
}
__device__ __forceinline__ void mma16816(float &c0, float &c1, float &c2, float &c3,
                                         unsigned a0, unsigned a1, unsigned a2, unsigned a3,
                                         unsigned b0, unsigned b1) {
    asm volatile("mma.sync.aligned.m16n8k16.row.col.f32.f16.f16.f32 "
        "{%0,%1,%2,%3},{%4,%5,%6,%7},{%8,%9},{%0,%1,%2,%3};"
        : "+f"(c0), "+f"(c1), "+f"(c2), "+f"(c3)
        : "r"(a0), "r"(a1), "r"(a2), "r"(a3), "r"(b0), "r"(b1));
}

__global__ void __launch_bounds__(NT, 2) fused_kernel(
    const float* __restrict__ tokens,
    const void*  __restrict__ labels_v,
    const float* __restrict__ protos_g,
    float* __restrict__ out)
{
    __shared__ float su[NUM_PROTO];
    __shared__ int   s_cnt;

    float* sS   = (float*)(smc + OFFB_S);
    float* sv   = (float*)(smc + OFFB_SV);
    float* invn = (float*)(smc + OFFB_INVN);
    int*   idx  = (int*)(smc + OFFB_IDX);

    const int c    = blockIdx.x;
    const int tid  = threadIdx.x;
    const int lane = tid & 31;
    const int wid  = tid >> 5;

    if (tid == 0) s_cnt = 0;
    if (tid < NUM_PROTO) su[tid] = 0.f;
    if (tid < MC)        sv[tid] = 0.f;
    // zero pi_h (rows 10-15 and cols >= m must be 0 for the phase-4 MMA)
    for (int t = tid; t < 16 * PIK / 2; t += NT)
        ((unsigned*)(smc + OFFB_PIH))[t] = 0u;

    // ---- dtype detect: int64 labels (<200) have zero high words ----
    unsigned hwd = ((const unsigned*)labels_v)[2 * tid + 1];
    const int is64 = __syncthreads_or(hwd != 0u) ? 0 : 1;  // barrier orders init

    // ---- proto fp32 -> fp16 smem [rows 0-9 valid] ----
    {
        const float4* pg = (const float4*)(protos_g + (size_t)c * NUM_PROTO * EMBED_D);
        for (int t = tid; t < NUM_PROTO * EMBED_D / 4; t += NT) {
            float4 v = pg[t];
            int p = t >> 7, d4 = t & 127;
            __half2* dst = (__half2*)(smc + OFFB_PROTOH + p * ROWB) + d4 * 2;
            dst[0] = __floats2half2_rn(v.x, v.y);
            dst[1] = __floats2half2_rn(v.z, v.w);
        }
    }

    // ---- label scan: wide int4 loads, all in flight at once ----
    if (is64) {
        int4 v[8];
        const int4* L = (const int4*)labels_v;          // 2 labels per int4
        #pragma unroll
        for (int k = 0; k < 8; k++) v[k] = L[tid + NT * k];
        #pragma unroll
        for (int k = 0; k < 8; k++) {
            int base = 2 * (tid + NT * k);
            if (v[k].x == c) { int p = atomicAdd(&s_cnt, 1); if (p < MC) idx[p] = base; }
            if (v[k].z == c) { int p = atomicAdd(&s_cnt, 1); if (p < MC) idx[p] = base + 1; }
        }
    } else {
        int4 v[4];
        const int4* L = (const int4*)labels_v;          // 4 labels per int4
        #pragma unroll
        for (int k = 0; k < 4; k++) v[k] = L[tid + NT * k];
        #pragma unroll
        for (int k = 0; k < 4; k++) {
            int base = 4 * (tid + NT * k);
            if (v[k].x == c) { int p = atomicAdd(&s_cnt, 1); if (p < MC) idx[p] = base; }
            if (v[k].y == c) { int p = atomicAdd(&s_cnt, 1); if (p < MC) idx[p] = base + 1; }
            if (v[k].z == c) { int p = atomicAdd(&s_cnt, 1); if (p < MC) idx[p] = base + 2; }
            if (v[k].w == c) { int p = atomicAdd(&s_cnt, 1); if (p < MC) idx[p] = base + 3; }
        }
    }
    __syncthreads();
    const int m    = (s_cnt < MC) ? s_cnt : MC;
    const int mcap = (m < TCAP) ? m : TCAP;
    const int ks   = (mcap + 15) >> 4;          // phase-4 k-steps

    // ---- Pre-pass: warp per row: load fp32, normalize, stage fp16 ----
    for (int j = wid; j < m; j += 16) {
        const float4* tk = (const float4*)(tokens + (size_t)idx[j] * EMBED_D);
        float4 r[4];
        float ss = 0.f;
        #pragma unroll
        for (int k = 0; k < 4; k++) {
            r[k] = tk[lane + 32 * k];
            ss += r[k].x*r[k].x + r[k].y*r[k].y + r[k].z*r[k].z + r[k].w*r[k].w;
        }
        #pragma unroll
        for (int o = 16; o; o >>= 1) ss += __shfl_xor_sync(0xffffffffu, ss, o);
        float inv = rsqrtf(ss);
        if (lane == 0) invn[j] = inv;
        if (j < TCAP) {
            __half2* row = (__half2*)(smc + OFFB_TOKH + j * ROWB);
            #pragma unroll
            for (int k = 0; k < 4; k++) {
                int h2 = (lane + 32 * k) * 2;
                row[h2]     = __floats2half2_rn(r[k].x * inv, r[k].y * inv);
                row[h2 + 1] = __floats2half2_rn(r[k].z * inv, r[k].w * inv);
            }
        }
    }
    // zero tok_h rows [mcap, 16*ks) — read by phase-4 MMA, never staged
    for (int t = tid; t < (16 * ks - mcap) * 260; t += NT) {
        int r = mcap + t / 260, q = t % 260;
        *((unsigned*)(smc + OFFB_TOKH + r * ROWB) + q) = 0u;
    }
    __syncthreads();

    // ---- Phase 2: S = proto @ tok_norm^T via tensor cores ----
    if (wid < 8) {
        const int jt = wid * 8;
        const int g  = lane >> 3;
        const int r8 = lane & 7;
        unsigned a_base = (unsigned)__cvta_generic_to_shared(
            smc + OFFB_PROTOH + ((g & 1) * 8 + r8) * ROWB + (g >> 1) * 16);
        unsigned b_base = (unsigned)__cvta_generic_to_shared(
            smc + OFFB_TOKH + (jt + r8) * ROWB + (g & 1) * 16);
        float c0 = 0.f, c1 = 0.f, c2 = 0.f, c3 = 0.f;
        #pragma unroll 8
        for (int kk = 0; kk < 32; kk++) {
            unsigned a0, a1, a2, a3, b0, b1;
            ldm_x4(a_base + kk * 32, a0, a1, a2, a3);
            ldm_x2(b_base + kk * 32, b0, b1);
            mma16816(c0, c1, c2, c3, a0, a1, a2, a3, b0, b1);
        }
        const int row = lane >> 2;
        const int j0  = jt + 2 * (lane & 3);
        sS[row * MC + j0]     = c0;
        sS[row * MC + j0 + 1] = c1;
        if (row + 8 < NUM_PROTO) {
            sS[(row + 8) * MC + j0]     = c2;
            sS[(row + 8) * MC + j0 + 1] = c3;
        }
    } else if (m > TCAP) {
        // rare fallback: rows 64..m-1 from raw fp32 global -> needs invn
        for (int j = TCAP + (wid - 8); j < m; j += 8) {
            const float4* tk = (const float4*)(tokens + (size_t)idx[j] * EMBED_D + 16 * lane);
            float4 t[4];
            #pragma unroll
            for (int k = 0; k < 4; k++) t[k] = tk[k];
            float iv = invn[j];
            #pragma unroll
            for (int p = 0; p < NUM_PROTO; p++) {
                const __half2* ph = (const __half2*)(smc + OFFB_PROTOH + p * ROWB) + lane * 8;
                float d = 0.f;
                #pragma unroll
                for (int k = 0; k < 4; k++) {
                    float2 f0 = __half22float2(ph[2 * k]);
                    float2 f1 = __half22float2(ph[2 * k + 1]);
                    d += f0.x * t[k].x + f0.y * t[k].y + f1.x * t[k].z + f1.y * t[k].w;
                }
                #pragma unroll
                for (int o = 16; o; o >>= 1) d += __shfl_xor_sync(0xffffffffu, d, o);
                if (lane == 0) sS[p * MC + j] = d * iv;
            }
        }
    }
    __syncthreads();

    // ---- Phase 3: Sinkhorn (warps 0-9; named barrier 1, 320 threads) ----
    if (m > 0 && wid < NUM_PROTO) {
        const float log_a = __logf(1.0f / (float)NUM_PROTO + 1e-8f);
        const float log_b = __logf(1.0f / (float)m + 1e-8f);
        const float inv_eps = 1.0f / EPSILON_;
        const int p = wid;

        const float s0 = (lane      < m) ? sS[p * MC + lane]      : -INFINITY;
        const float s1 = (lane + 32 < m) ? sS[p * MC + lane + 32] : -INFINITY;
        const float s2 = (lane + 64 < m) ? sS[p * MC + lane + 64] : -INFINITY;
        float scol[NUM_PROTO];
        if (tid < m) {
            #pragma unroll
            for (int pp = 0; pp < NUM_PROTO; pp++) scol[pp] = sS[pp * MC + tid];
        }

        for (int it = 0; it < ITERS; it++) {
            {
                float up = su[p];
                float t0 = (s0 + up + sv[lane])      * inv_eps;
                float t1 = (s1 + up + sv[lane + 32]) * inv_eps;
                float t2 = (s2 + up + sv[lane + 64]) * inv_eps;
                float mx = fmaxf(t0, fmaxf(t1, t2));
                #pragma unroll
                for (int o = 16; o; o >>= 1)
                    mx = fmaxf(mx, __shfl_xor_sync(0xffffffffu, mx, o));
                float sum = __expf(t0 - mx) + __expf(t1 - mx) + __expf(t2 - mx);
                #pragma unroll
                for (int o = 16; o; o >>= 1)
                    sum += __shfl_xor_sync(0xffffffffu, sum, o);
                if (lane == 0)
                    su[p] = EPSILON_ * (log_a - (mx + __logf(sum))) + up;
            }
            asm volatile("bar.sync 1, 320;" ::: "memory");
            if (tid < m) {
                float vj = sv[tid];
                float mx = -INFINITY;
                #pragma unroll
                for (int pp = 0; pp < NUM_PROTO; pp++)
                    mx = fmaxf(mx, (scol[pp] + su[pp] + vj) * inv_eps);
                float sum = 0.f;
                #pragma unroll
                for (int pp = 0; pp < NUM_PROTO; pp++)
                    sum += __expf((scol[pp] + su[pp] + vj) * inv_eps - mx);
                sv[tid] = EPSILON_ * (log_b - (mx + __logf(sum))) + vj;
            }
            asm volatile("bar.sync 1, 320;" ::: "memory");
        }

        if (tid < m) {   // pi, column-normalized; fp32 to sS (fallback) + fp16 to pi_h (MMA)
            float vj = sv[tid];
            float col[NUM_PROTO];
            float cs = 0.f;
            #pragma unroll
            for (int pp = 0; pp < NUM_PROTO; pp++) {
                col[pp] = __expf((scol[pp] + su[pp] + vj) * inv_eps);
                cs += col[pp];
            }
            float inv = 1.0f / cs;
            __half* ph = (__half*)(smc + OFFB_PIH);
            #pragma unroll
            for (int pp = 0; pp < NUM_PROTO; pp++) {
                float w = col[pp] * inv;
                sS[pp * MC + tid] = w;
                ph[pp * PIK + tid] = __float2half(w);
            }
        }
    }
    __syncthreads();

    // ---- Phase 4: new_proto = pi_ @ tok via tensor cores ----
    // Warp w: n-columns [32w, 32w+32) as 4 n-tiles of 8; A = pi_h [16][PIK],
    // B = tok_h rows (trans). C -> stage [10][516] fp32 (reuses tok area).
    float* stage = (float*)(smc + OFFB_TOKH);
    {
        float cc[4][4];
        #pragma unroll
        for (int nt = 0; nt < 4; nt++)
            #pragma unroll
            for (int q = 0; q < 4; q++) cc[nt][q] = 0.f;

        const int g  = lane >> 3;
        const int r8 = lane & 7;
        unsigned a_base = (unsigned)__cvta_generic_to_shared(
            smc + OFFB_PIH + ((g & 1) * 8 + r8) * (PIK * 2) + (g >> 1) * 16);
        const int brow = lane & 15;
        for (int k = 0; k < ks; k++) {
            unsigned a0, a1, a2, a3;
            ldm_x4(a_base + k * 32, a0, a1, a2, a3);
            #pragma unroll
            for (int nt = 0; nt < 4; nt++) {
                unsigned b0, b1;
                unsigned b_addr = (unsigned)__cvta_generic_to_shared(
                    smc + OFFB_TOKH + (k * 16 + brow) * ROWB + (wid * 32 + nt * 8) * 2);
                ldm_x2t(b_addr, b0, b1);
                mma16816(cc[nt][0], cc[nt][1], cc[nt][2], cc[nt][3],
                         a0, a1, a2, a3, b0, b1);
            }
        }
        if (mcap == 0) {    // degenerate guard: stage must be defined
            for (int t = tid; t < NUM_PROTO * STG_W; t += NT) stage[t] = 0.f;
        }
        __syncthreads();    // all MMA reads of tok_h done before stage overwrite

        const int row  = lane >> 2;
        const int tcol = lane & 3;
        #pragma unroll
        for (int nt = 0; nt < 4; nt++) {
            int n = wid * 32 + nt * 8 + 2 * tcol;
            if (row < NUM_PROTO)
                *(float2*)(stage + row * STG_W + n) = make_float2(cc[nt][0], cc[nt][1]);
            if (row + 8 < NUM_PROTO)
                *(float2*)(stage + (row + 8) * STG_W + n) = make_float2(cc[nt][2], cc[nt][3]);
        }
    }
    __syncthreads();

    if (m > TCAP) {     // rare: add rows 64..m-1 scalar contributions
        for (int j = TCAP; j < m; j++) {
            float iv = invn[j];
            const float* tr = tokens + (size_t)idx[j] * EMBED_D;
            for (int d = tid; d < EMBED_D; d += NT) {
                float t = tr[d] * iv;
                #pragma unroll
                for (int p = 0; p < NUM_PROTO; p++)
                    stage[p * STG_W + d] += sS[p * MC + j] * t;
            }
        }
        __syncthreads();
    }

    // ---- epilogue: warp p blends, l2-normalizes, writes ----
    if (wid < NUM_PROTO) {
        const int p = wid;
        float2 v[8];
        float ss = 0.f;
        const float2* pr2 = (const float2*)(protos_g + ((size_t)c * NUM_PROTO + p) * EMBED_D);
        const float2* srow = (const float2*)(stage + p * STG_W);
        #pragma unroll
        for (int qq = 0; qq < 8; qq++) {
            int dd = lane + 32 * qq;
            float2 a = srow[dd];
            float2 pr = pr2[dd];
            v[qq].x = (1.0f - MOM) * pr.x + MOM * a.x;
            v[qq].y = (1.0f - MOM) * pr.y + MOM * a.y;
            ss += v[qq].x * v[qq].x + v[qq].y * v[qq].y;
        }
        #pragma unroll
        for (int o = 16; o; o >>= 1) ss += __shfl_xor_sync(0xffffffffu, ss, o);
        float inv = rsqrtf(ss);
        float2* dst = (float2*)(out + ((size_t)(c * NUM_PROTO + p)) * EMBED_D);
        #pragma unroll
        for (int qq = 0; qq < 8; qq++) {
            float2 o2;
            o2.x = v[qq].x * inv;
            o2.y = v[qq].y * inv;
            dst[lane + 32 * qq] = o2;
        }
    }
}

// ---------------------------------------------------------------------------
extern "C" void kernel_launch(void* const* d_in, const int* in_sizes, int n_in,
                              void* d_out, int out_size) {
    const float* tokens = (const float*)d_in[0];
    const void*  labels = d_in[1];
    const float* protos = (const float*)d_in[2];
    float* out = (float*)d_out;

    cudaFuncSetAttribute(fused_kernel,
                         cudaFuncAttributeMaxDynamicSharedMemorySize, SMEM_BYTES);
    fused_kernel<<<NUM_CLASSES, NT, SMEM_BYTES>>>(tokens, labels, protos, out);
}